// round 13
// baseline (speedup 1.0000x reference)
#include <cuda_runtime.h>
#include <math.h>
#include <stdint.h>

// Causal depthwise conv1d K=24, T=3000 as banded tf32 GEMM via mma.sync.
// Per channel c, per 16-wide t-tile:
//   Y[m][n] = sum_k A[m][k] * B[k][n],  m=t-in-tile(16), n=batch(16), k=0..39
//   A[m][k] = w[k-m-1] if 0<=k-m-1<24 else 0   (tile-invariant band)
//   B[k][n] = x[n, c, t0-24+k]                 (staged in smem, tf32-rounded)
// since y[t0+m] = sum_j w[j] x[t0+m-23+j], with k = m+j+1 in [1,39].

#define C_DIM 1024
#define T_LEN 3000
#define KSZ 24
#define SEGLEN 752              // 47 tiles * 16
#define NTILES 47
#define HALO 24
#define ROWF 776                // HALO + SEGLEN floats staged per row
#define RSTRIDE 804             // floats; 804 % 32 == 4 -> B-frag LDS conflict-free
#define NB 16
#define NTHREADS 256
#define PSTRIDE 18              // patch row stride; conflict-free readback
#define PATCHF (16 * PSTRIDE)
#define XS_F (NB * RSTRIDE)                 // 12864 floats
#define PATCH_BASE XS_F
#define SW_BASE (XS_F + 8 * PATCHF)         // 15168
#define SMEM_BYTES ((SW_BASE + 32) * 4)     // 60800

__device__ __forceinline__ uint32_t f2tf32(float f) {
    uint32_t u;
    asm("cvt.rna.tf32.f32 %0, %1;" : "=r"(u) : "f"(f));
    return u;
}

__device__ __forceinline__ void mma_tf32(float* d, const uint32_t* a,
                                         uint32_t b0, uint32_t b1) {
    asm volatile(
        "mma.sync.aligned.m16n8k8.row.col.f32.tf32.tf32.f32 "
        "{%0,%1,%2,%3}, {%4,%5,%6,%7}, {%8,%9}, {%0,%1,%2,%3};"
        : "+f"(d[0]), "+f"(d[1]), "+f"(d[2]), "+f"(d[3])
        : "r"(a[0]), "r"(a[1]), "r"(a[2]), "r"(a[3]), "r"(b0), "r"(b1));
}

__global__ __launch_bounds__(NTHREADS)
void ssm4d_mma_kernel(const float* __restrict__ x,
                      const float* __restrict__ alpha,
                      const float* __restrict__ beta,
                      const float* __restrict__ theta,
                      float* __restrict__ y)
{
    extern __shared__ float sm[];
    float* xs = sm;                       // [NB][RSTRIDE]
    float* sw = sm + SW_BASE;             // 24 tf32-rounded weights

    const int c    = blockIdx.x;
    const int seg  = blockIdx.y;
    const int tid  = threadIdx.x;
    const int wid  = tid >> 5;
    const int lane = tid & 31;
    const int grp  = lane >> 2;           // groupID = lane/4
    const int thr  = lane & 3;            // threadID in group
    const int seg_base = seg * SEGLEN;
    const int CT = C_DIM * T_LEN;

    float* patch = sm + PATCH_BASE + wid * PATCHF;

    // ---- per-channel weights, tf32-rounded ----
    if (tid < KSZ) {
        float a  = alpha[c];
        float la = logf(fmaxf(a, 1e-6f));
        float d  = expf(la * (float)tid);
        float u  = theta[c] * (float)tid;
        float u2 = u * u;
        float ph = 1.0f - 0.5f * u2 + (u2 * u2) * (1.0f / 24.0f);
        float wv = beta[c] * d * ph;
        sw[tid] = __uint_as_float(f2tf32(wv));
    }

    // ---- stage x rows (16 batches), tf32-rounded, zero-padded ----
    // xs[n][p] = tf32(x[n, c, seg_base - 24 + p]), p in [0, ROWF)
    for (int i = tid; i < NB * (ROWF / 4); i += NTHREADS) {
        int n = i / (ROWF / 4);
        int v = i % (ROWF / 4);
        int t = seg_base - HALO + 4 * v;
        const float* src = x + n * CT + c * T_LEN;
        float4 vv;
        if (t >= 0 && t + 3 < T_LEN) {
            vv = *reinterpret_cast<const float4*>(src + t);
        } else {
            vv.x = (t + 0 >= 0 && t + 0 < T_LEN) ? src[t + 0] : 0.0f;
            vv.y = (t + 1 >= 0 && t + 1 < T_LEN) ? src[t + 1] : 0.0f;
            vv.z = (t + 2 >= 0 && t + 2 < T_LEN) ? src[t + 2] : 0.0f;
            vv.w = (t + 3 >= 0 && t + 3 < T_LEN) ? src[t + 3] : 0.0f;
        }
        vv.x = __uint_as_float(f2tf32(vv.x));
        vv.y = __uint_as_float(f2tf32(vv.y));
        vv.z = __uint_as_float(f2tf32(vv.z));
        vv.w = __uint_as_float(f2tf32(vv.w));
        *reinterpret_cast<float4*>(&xs[n * RSTRIDE + 4 * v]) = vv;
    }
    __syncthreads();

    // ---- A fragments (tile-invariant): 5 k-chunks x 4 regs ----
    // a0=(grp, k0), a1=(grp+8, k0), a2=(grp, k0+4), a3=(grp+8, k0+4)
    uint32_t afr[5][4];
#pragma unroll
    for (int cc = 0; cc < 5; cc++) {
        int k0 = cc * 8 + thr;
        int j;
        j = k0 - grp - 1;
        afr[cc][0] = (j >= 0 && j < KSZ) ? __float_as_uint(sw[j]) : 0u;
        j = k0 - (grp + 8) - 1;
        afr[cc][1] = (j >= 0 && j < KSZ) ? __float_as_uint(sw[j]) : 0u;
        j = (k0 + 4) - grp - 1;
        afr[cc][2] = (j >= 0 && j < KSZ) ? __float_as_uint(sw[j]) : 0u;
        j = (k0 + 4) - (grp + 8) - 1;
        afr[cc][3] = (j >= 0 && j < KSZ) ? __float_as_uint(sw[j]) : 0u;
    }

    // ---- tile loop: warps round-robin over 47 tiles ----
    for (int tile = wid; tile < NTILES; tile += 8) {
        const int base = tile * 16;           // window start in xs
        const int t0g  = seg_base + tile * 16;

        float acc[2][4];
#pragma unroll
        for (int h = 0; h < 2; h++)
#pragma unroll
            for (int r = 0; r < 4; r++) acc[h][r] = 0.0f;

#pragma unroll
        for (int cc = 0; cc < 5; cc++) {
            const int kb = base + cc * 8 + thr;
            // h = 0: n = grp; h = 1: n = grp + 8
            uint32_t b0a = __float_as_uint(xs[grp * RSTRIDE + kb]);
            uint32_t b1a = __float_as_uint(xs[grp * RSTRIDE + kb + 4]);
            uint32_t b0b = __float_as_uint(xs[(grp + 8) * RSTRIDE + kb]);
            uint32_t b1b = __float_as_uint(xs[(grp + 8) * RSTRIDE + kb + 4]);
            mma_tf32(acc[0], afr[cc], b0a, b1a);
            mma_tf32(acc[1], afr[cc], b0b, b1b);
        }

        // ---- epilogue: transpose via warp-private smem patch ----
        // D layout: c0=(grp, 2thr), c1=(grp, 2thr+1), c2=(grp+8, 2thr),
        // c3=(grp+8, 2thr+1); global col n = 8h + col.
#pragma unroll
        for (int h = 0; h < 2; h++) {
            patch[grp * PSTRIDE + 8 * h + 2 * thr]           = acc[h][0];
            patch[grp * PSTRIDE + 8 * h + 2 * thr + 1]       = acc[h][1];
            patch[(grp + 8) * PSTRIDE + 8 * h + 2 * thr]     = acc[h][2];
            patch[(grp + 8) * PSTRIDE + 8 * h + 2 * thr + 1] = acc[h][3];
        }
        __syncwarp();

        // readback: flat = 32q + lane -> n = flat/4, t4 = flat%4
#pragma unroll
        for (int q = 0; q < 2; q++) {
            int flat = 32 * q + lane;
            int n  = flat >> 2;
            int t4 = flat & 3;
            int tg = t0g + 4 * t4;
            if (tg < T_LEN) {
                float4 o;
                o.x = patch[(4 * t4 + 0) * PSTRIDE + n];
                o.y = patch[(4 * t4 + 1) * PSTRIDE + n];
                o.z = patch[(4 * t4 + 2) * PSTRIDE + n];
                o.w = patch[(4 * t4 + 3) * PSTRIDE + n];
                *reinterpret_cast<float4*>(y + n * CT + c * T_LEN + tg) = o;
            }
        }
        __syncwarp();   // patch reusable next tile
    }
}

extern "C" void kernel_launch(void* const* d_in, const int* in_sizes, int n_in,
                              void* d_out, int out_size)
{
    const float* x     = (const float*)d_in[0];
    const float* alpha = (const float*)d_in[1];
    const float* beta  = (const float*)d_in[2];
    const float* theta = (const float*)d_in[3];
    float* y = (float*)d_out;

    cudaFuncSetAttribute(ssm4d_mma_kernel,
                         cudaFuncAttributeMaxDynamicSharedMemorySize,
                         SMEM_BYTES);
    dim3 grid(C_DIM, 4);   // 4 segments of 752 cover T=3000 (last predicated)
    ssm4d_mma_kernel<<<grid, NTHREADS, SMEM_BYTES>>>(x, alpha, beta, theta, y);
}

// round 14
// speedup vs baseline: 1.2399x; 1.2399x over previous
#include <cuda_runtime.h>
#include <math.h>
#include <stdint.h>

// Causal depthwise conv1d K=24, T=3000 as banded tf32 GEMM via mma.sync.
// Per channel c, per 16-wide t-tile:
//   Y[m][n] = sum_k A[m][k] * B[k][n],  m=t-in-tile(16), n=batch(16), k=0..39
//   A[m][k] = w[k-m-1] if 0<=k-m-1<24 else 0   (tile-invariant band)
//   B[k][n] = x[n, c, t0-24+k]                 (staged in smem, tf32-rounded)
// R14: R13 math, R6 geometry — seg=384 (24 tiles), 35.4KB smem, 6 CTAs/SM,
//      grid 8192, div-free staging. Epilogue patch transpose unchanged.

#define C_DIM 1024
#define T_LEN 3000
#define KSZ 24
#define SEGLEN 384
#define NTILES 24
#define HALO 24
#define ROWF 408                 // floats staged per row (halo + seg)
#define ROWF4 102                // float4 per row
#define RSTRIDE 420              // 420 % 32 == 4 -> B-frag LDS conflict-free
#define NB 16
#define NTHREADS 256
#define PSTRIDE 18               // patch row stride, conflict-free readback
#define PATCHF (16 * PSTRIDE)    // 288
#define XS_F (NB * RSTRIDE)               // 6720
#define PATCH_BASE XS_F
#define SW_BASE (XS_F + 8 * PATCHF)       // 9024
#define SMEM_BYTES ((SW_BASE + 32) * 4)   // 36224

__device__ __forceinline__ uint32_t f2tf32(float f) {
    uint32_t u;
    asm("cvt.rna.tf32.f32 %0, %1;" : "=r"(u) : "f"(f));
    return u;
}

__device__ __forceinline__ void mma_tf32(float* d, const uint32_t* a,
                                         uint32_t b0, uint32_t b1) {
    asm volatile(
        "mma.sync.aligned.m16n8k8.row.col.f32.tf32.tf32.f32 "
        "{%0,%1,%2,%3}, {%4,%5,%6,%7}, {%8,%9}, {%0,%1,%2,%3};"
        : "+f"(d[0]), "+f"(d[1]), "+f"(d[2]), "+f"(d[3])
        : "r"(a[0]), "r"(a[1]), "r"(a[2]), "r"(a[3]), "r"(b0), "r"(b1));
}

__global__ __launch_bounds__(NTHREADS, 6)
void ssm4d_mma_kernel(const float* __restrict__ x,
                      const float* __restrict__ alpha,
                      const float* __restrict__ beta,
                      const float* __restrict__ theta,
                      float* __restrict__ y)
{
    extern __shared__ float sm[];
    float* xs = sm;                       // [NB][RSTRIDE]
    float* sw = sm + SW_BASE;             // 24 tf32-rounded weights

    const int c    = blockIdx.x;
    const int seg  = blockIdx.y;
    const int tid  = threadIdx.x;
    const int wid  = tid >> 5;
    const int lane = tid & 31;
    const int grp  = lane >> 2;           // groupID = lane/4
    const int thr  = lane & 3;            // threadID in group
    const int seg_base = seg * SEGLEN;
    const int CT = C_DIM * T_LEN;

    float* patch = sm + PATCH_BASE + wid * PATCHF;

    // ---- per-channel weights, tf32-rounded ----
    if (tid < KSZ) {
        float a  = alpha[c];
        float la = logf(fmaxf(a, 1e-6f));
        float d  = expf(la * (float)tid);
        float u  = theta[c] * (float)tid;
        float u2 = u * u;
        float ph = 1.0f - 0.5f * u2 + (u2 * u2) * (1.0f / 24.0f);
        float wv = beta[c] * d * ph;
        sw[tid] = __uint_as_float(f2tf32(wv));
    }

    // ---- stage x (16 rows x 408 floats), tf32-rounded, zero-padded ----
    // 16 threads per row; div-free indexing; aligned LDG.128 on interior.
    {
        const int nrow = tid >> 4;        // 0..15
        const int lv   = tid & 15;
        const float* src = x + nrow * CT + c * T_LEN;
        float* dst = xs + nrow * RSTRIDE;
#pragma unroll
        for (int it = 0; it < 7; it++) {
            int v = lv + 16 * it;
            if (v < ROWF4) {
                int t = seg_base - HALO + 4 * v;
                float4 vv;
                if (t >= 0 && t + 3 < T_LEN) {
                    vv = *reinterpret_cast<const float4*>(src + t);
                } else {
                    vv.x = (t + 0 >= 0 && t + 0 < T_LEN) ? src[t + 0] : 0.0f;
                    vv.y = (t + 1 >= 0 && t + 1 < T_LEN) ? src[t + 1] : 0.0f;
                    vv.z = (t + 2 >= 0 && t + 2 < T_LEN) ? src[t + 2] : 0.0f;
                    vv.w = (t + 3 >= 0 && t + 3 < T_LEN) ? src[t + 3] : 0.0f;
                }
                vv.x = __uint_as_float(f2tf32(vv.x));
                vv.y = __uint_as_float(f2tf32(vv.y));
                vv.z = __uint_as_float(f2tf32(vv.z));
                vv.w = __uint_as_float(f2tf32(vv.w));
                *reinterpret_cast<float4*>(dst + 4 * v) = vv;
            }
        }
    }
    __syncthreads();

    // ---- A fragments (tile-invariant): 5 k-chunks x 4 regs ----
    uint32_t afr[5][4];
#pragma unroll
    for (int cc = 0; cc < 5; cc++) {
        int k0 = cc * 8 + thr;
        int j;
        j = k0 - grp - 1;
        afr[cc][0] = (j >= 0 && j < KSZ) ? __float_as_uint(sw[j]) : 0u;
        j = k0 - (grp + 8) - 1;
        afr[cc][1] = (j >= 0 && j < KSZ) ? __float_as_uint(sw[j]) : 0u;
        j = (k0 + 4) - grp - 1;
        afr[cc][2] = (j >= 0 && j < KSZ) ? __float_as_uint(sw[j]) : 0u;
        j = (k0 + 4) - (grp + 8) - 1;
        afr[cc][3] = (j >= 0 && j < KSZ) ? __float_as_uint(sw[j]) : 0u;
    }

    const float* xr0 = xs + grp * RSTRIDE;
    const float* xr1 = xs + (grp + 8) * RSTRIDE;

    // ---- tile loop: 24 tiles, 8 warps -> 3 tiles/warp, no divergence ----
#pragma unroll
    for (int tile = wid; tile < NTILES; tile += 8) {
        const int base = tile * 16;
        const int t0g  = seg_base + tile * 16;

        float acc[2][4];
#pragma unroll
        for (int h = 0; h < 2; h++)
#pragma unroll
            for (int r = 0; r < 4; r++) acc[h][r] = 0.0f;

#pragma unroll
        for (int cc = 0; cc < 5; cc++) {
            const int kb = base + cc * 8 + thr;
            uint32_t b0a = __float_as_uint(xr0[kb]);
            uint32_t b1a = __float_as_uint(xr0[kb + 4]);
            uint32_t b0b = __float_as_uint(xr1[kb]);
            uint32_t b1b = __float_as_uint(xr1[kb + 4]);
            mma_tf32(acc[0], afr[cc], b0a, b1a);
            mma_tf32(acc[1], afr[cc], b0b, b1b);
        }

        // epilogue: transpose via warp-private smem patch, coalesced STG.128
#pragma unroll
        for (int h = 0; h < 2; h++) {
            patch[grp * PSTRIDE + 8 * h + 2 * thr]           = acc[h][0];
            patch[grp * PSTRIDE + 8 * h + 2 * thr + 1]       = acc[h][1];
            patch[(grp + 8) * PSTRIDE + 8 * h + 2 * thr]     = acc[h][2];
            patch[(grp + 8) * PSTRIDE + 8 * h + 2 * thr + 1] = acc[h][3];
        }
        __syncwarp();

#pragma unroll
        for (int q = 0; q < 2; q++) {
            int flat = 32 * q + lane;
            int n  = flat >> 2;
            int t4 = flat & 3;
            int tg = t0g + 4 * t4;
            if (tg < T_LEN) {
                float4 o;
                o.x = patch[(4 * t4 + 0) * PSTRIDE + n];
                o.y = patch[(4 * t4 + 1) * PSTRIDE + n];
                o.z = patch[(4 * t4 + 2) * PSTRIDE + n];
                o.w = patch[(4 * t4 + 3) * PSTRIDE + n];
                *reinterpret_cast<float4*>(y + n * CT + c * T_LEN + tg) = o;
            }
        }
        __syncwarp();   // patch reusable next tile
    }
}

extern "C" void kernel_launch(void* const* d_in, const int* in_sizes, int n_in,
                              void* d_out, int out_size)
{
    const float* x     = (const float*)d_in[0];
    const float* alpha = (const float*)d_in[1];
    const float* beta  = (const float*)d_in[2];
    const float* theta = (const float*)d_in[3];
    float* y = (float*)d_out;

    cudaFuncSetAttribute(ssm4d_mma_kernel,
                         cudaFuncAttributeMaxDynamicSharedMemorySize,
                         SMEM_BYTES);
    dim3 grid(C_DIM, 8);   // 8 segments of 384 cover T=3000 (tail predicated)
    ssm4d_mma_kernel<<<grid, NTHREADS, SMEM_BYTES>>>(x, alpha, beta, theta, y);
}

// round 15
// speedup vs baseline: 1.7763x; 1.4327x over previous
#include <cuda_runtime.h>
#include <math.h>
#include <stdint.h>

// Causal depthwise conv1d K=24, T=3000 as banded tf32 GEMM via mma.sync.
// Per channel c, per 16-wide t-tile:
//   Y[m][n] = sum_k A[m][k] * B[k][n],  m=t-in-tile(16), n=batch(16), k=0..39
//   A[m][k] = w[k-m-1] if 0<=k-m-1<24 else 0   (tile-invariant band)
//   B[k][n] = x[n, c, t0-24+k]
// R15: R14 with TMA bulk staging (raw floats, no LDG/STS/cvt in fill) and
//      use-time cvt.rna on B fragments (numerics identical to R13/R14).

#define C_DIM 1024
#define T_LEN 3000
#define KSZ 24
#define SEGLEN 384
#define NTILES 24
#define HALO 24
#define ROWF 408                 // floats staged per row (halo + seg)
#define RSTRIDE 420              // 420 % 32 == 4 -> B-frag LDS conflict-free
#define NB 16
#define NTHREADS 256
#define PSTRIDE 18               // patch row stride, conflict-free readback
#define PATCHF (16 * PSTRIDE)    // 288
#define XS_F (NB * RSTRIDE)               // 6720
#define PATCH_BASE XS_F
#define SW_BASE (XS_F + 8 * PATCHF)       // 9024
#define MBAR_F (SW_BASE + 24)             // 8B-aligned (even float index)
#define SMEM_BYTES ((MBAR_F + 8) * 4)

__device__ __forceinline__ uint32_t f2tf32(float f) {
    uint32_t u;
    asm("cvt.rna.tf32.f32 %0, %1;" : "=r"(u) : "f"(f));
    return u;
}

__device__ __forceinline__ void mma_tf32(float* d, const uint32_t* a,
                                         uint32_t b0, uint32_t b1) {
    asm volatile(
        "mma.sync.aligned.m16n8k8.row.col.f32.tf32.tf32.f32 "
        "{%0,%1,%2,%3}, {%4,%5,%6,%7}, {%8,%9}, {%0,%1,%2,%3};"
        : "+f"(d[0]), "+f"(d[1]), "+f"(d[2]), "+f"(d[3])
        : "r"(a[0]), "r"(a[1]), "r"(a[2]), "r"(a[3]), "r"(b0), "r"(b1));
}

__device__ __forceinline__ void mbar_wait(uint32_t mba, uint32_t parity) {
    uint32_t done;
    asm volatile(
        "{\n\t"
        ".reg .pred p;\n\t"
        "mbarrier.try_wait.parity.acquire.cta.shared::cta.b64 p, [%1], %2;\n\t"
        "selp.b32 %0, 1, 0, p;\n\t"
        "}"
        : "=r"(done) : "r"(mba), "r"(parity) : "memory");
    if (!done) {
        asm volatile(
            "{\n\t"
            ".reg .pred P1;\n\t"
            "WAIT_LOOP_%=:\n\t"
            "mbarrier.try_wait.parity.acquire.cta.shared::cta.b64 P1, [%0], %1, 0x989680;\n\t"
            "@P1 bra.uni WAIT_DONE_%=;\n\t"
            "bra.uni WAIT_LOOP_%=;\n\t"
            "WAIT_DONE_%=:\n\t"
            "}"
            :: "r"(mba), "r"(parity) : "memory");
    }
}

__global__ __launch_bounds__(NTHREADS, 6)
void ssm4d_mma_kernel(const float* __restrict__ x,
                      const float* __restrict__ alpha,
                      const float* __restrict__ beta,
                      const float* __restrict__ theta,
                      float* __restrict__ y)
{
    extern __shared__ float sm[];
    float* xs = sm;                       // [NB][RSTRIDE], raw floats
    float* sw = sm + SW_BASE;             // 24 tf32-rounded weights

    const int c    = blockIdx.x;
    const int seg  = blockIdx.y;
    const int tid  = threadIdx.x;
    const int wid  = tid >> 5;
    const int lane = tid & 31;
    const int grp  = lane >> 2;
    const int thr  = lane & 3;
    const int seg_base = seg * SEGLEN;
    const int CT = C_DIM * T_LEN;

    float* patch = sm + PATCH_BASE + wid * PATCHF;
    const uint32_t mba =
        (uint32_t)__cvta_generic_to_shared(sm + MBAR_F);

    // boundary clamping (all 16B-aligned by construction)
    const int copy_start = (seg_base - HALO < 0) ? 0 : seg_base - HALO;
    const int copy_end   = (seg_base + SEGLEN > T_LEN) ? T_LEN
                                                       : seg_base + SEGLEN;
    const int dst_off    = copy_start - (seg_base - HALO); // 0 or 24 floats
    const int len_f      = copy_end - copy_start;          // floats
    const int filled_end = dst_off + len_f;                // <= ROWF

    if (tid == 0) {
        asm volatile("mbarrier.init.shared.b64 [%0], 1;" :: "r"(mba) : "memory");
        asm volatile("mbarrier.arrive.expect_tx.shared.b64 _, [%0], %1;"
                     :: "r"(mba), "r"((uint32_t)(NB * len_f * 4)) : "memory");
    }

    // zero uncovered head/tail of each row (seg 0 head, last seg tail)
    if (tid < NB) {
        float4* row4 = reinterpret_cast<float4*>(xs + tid * RSTRIDE);
        for (int v = 0; v < dst_off / 4; v++)
            row4[v] = make_float4(0.f, 0.f, 0.f, 0.f);
        for (int v = filled_end / 4; v < ROWF / 4; v++)
            row4[v] = make_float4(0.f, 0.f, 0.f, 0.f);
    }
    // per-channel weights, tf32-rounded
    if (tid < KSZ) {
        float a  = alpha[c];
        float la = logf(fmaxf(a, 1e-6f));
        float d  = expf(la * (float)tid);
        float u  = theta[c] * (float)tid;
        float u2 = u * u;
        float ph = 1.0f - 0.5f * u2 + (u2 * u2) * (1.0f / 24.0f);
        sw[tid] = __uint_as_float(f2tf32(beta[c] * d * ph));
    }
    __syncthreads();   // mbar init + expect_tx + zeros + weights visible

    // TMA bulk staging: one copy per batch row (raw floats)
    if (tid < NB) {
        const float* src = x + tid * CT + c * T_LEN + copy_start;
        const uint32_t sdst = (uint32_t)__cvta_generic_to_shared(
            xs + tid * RSTRIDE + dst_off);
        asm volatile(
            "cp.async.bulk.shared::cluster.global.mbarrier::complete_tx::bytes "
            "[%0], [%1], %2, [%3];"
            :: "r"(sdst), "l"(src), "r"((uint32_t)(len_f * 4)), "r"(mba)
            : "memory");
    }

    // A fragments (tile-invariant): 5 k-chunks x 4 regs
    uint32_t afr[5][4];
#pragma unroll
    for (int cc = 0; cc < 5; cc++) {
        int k0 = cc * 8 + thr;
        int j;
        j = k0 - grp - 1;
        afr[cc][0] = (j >= 0 && j < KSZ) ? __float_as_uint(sw[j]) : 0u;
        j = k0 - (grp + 8) - 1;
        afr[cc][1] = (j >= 0 && j < KSZ) ? __float_as_uint(sw[j]) : 0u;
        j = (k0 + 4) - grp - 1;
        afr[cc][2] = (j >= 0 && j < KSZ) ? __float_as_uint(sw[j]) : 0u;
        j = (k0 + 4) - (grp + 8) - 1;
        afr[cc][3] = (j >= 0 && j < KSZ) ? __float_as_uint(sw[j]) : 0u;
    }

    mbar_wait(mba, 0u);   // staged x ready

    const float* xr0 = xs + grp * RSTRIDE;
    const float* xr1 = xs + (grp + 8) * RSTRIDE;

    // tile loop: 24 tiles, 8 warps -> 3 tiles/warp
#pragma unroll
    for (int tile = wid; tile < NTILES; tile += 8) {
        const int base = tile * 16;
        const int t0g  = seg_base + tile * 16;

        float acc[2][4];
#pragma unroll
        for (int h = 0; h < 2; h++)
#pragma unroll
            for (int r = 0; r < 4; r++) acc[h][r] = 0.0f;

#pragma unroll
        for (int cc = 0; cc < 5; cc++) {
            const int kb = base + cc * 8 + thr;
            // use-time tf32 rounding (numerics == R13/R14)
            uint32_t b0a = f2tf32(xr0[kb]);
            uint32_t b1a = f2tf32(xr0[kb + 4]);
            uint32_t b0b = f2tf32(xr1[kb]);
            uint32_t b1b = f2tf32(xr1[kb + 4]);
            mma_tf32(acc[0], afr[cc], b0a, b1a);
            mma_tf32(acc[1], afr[cc], b0b, b1b);
        }

        // epilogue: transpose via warp-private smem patch
#pragma unroll
        for (int h = 0; h < 2; h++) {
            *reinterpret_cast<float2*>(
                &patch[grp * PSTRIDE + 8 * h + 2 * thr]) =
                make_float2(acc[h][0], acc[h][1]);
            *reinterpret_cast<float2*>(
                &patch[(grp + 8) * PSTRIDE + 8 * h + 2 * thr]) =
                make_float2(acc[h][2], acc[h][3]);
        }
        __syncwarp();

#pragma unroll
        for (int q = 0; q < 2; q++) {
            int flat = 32 * q + lane;
            int n  = flat >> 2;
            int t4 = flat & 3;
            int tg = t0g + 4 * t4;
            if (tg < T_LEN) {
                float4 o;
                o.x = patch[(4 * t4 + 0) * PSTRIDE + n];
                o.y = patch[(4 * t4 + 1) * PSTRIDE + n];
                o.z = patch[(4 * t4 + 2) * PSTRIDE + n];
                o.w = patch[(4 * t4 + 3) * PSTRIDE + n];
                *reinterpret_cast<float4*>(y + n * CT + c * T_LEN + tg) = o;
            }
        }
        __syncwarp();   // patch reusable next tile
    }
}

extern "C" void kernel_launch(void* const* d_in, const int* in_sizes, int n_in,
                              void* d_out, int out_size)
{
    const float* x     = (const float*)d_in[0];
    const float* alpha = (const float*)d_in[1];
    const float* beta  = (const float*)d_in[2];
    const float* theta = (const float*)d_in[3];
    float* y = (float*)d_out;

    cudaFuncSetAttribute(ssm4d_mma_kernel,
                         cudaFuncAttributeMaxDynamicSharedMemorySize,
                         SMEM_BYTES);
    dim3 grid(C_DIM, 8);   // 8 segments of 384 cover T=3000 (tail predicated)
    ssm4d_mma_kernel<<<grid, NTHREADS, SMEM_BYTES>>>(x, alpha, beta, theta, y);
}